// round 2
// baseline (speedup 1.0000x reference)
#include <cuda_runtime.h>
#include <cstdint>

#define BB    32
#define NN    1024
#define ND    14
#define HID   64
#define HEADD 128
#define MAXN  64
#define ROWS  (BB*NN)          // 32768
#define RPB   64               // rows per block in agg/lin kernels
#define NBLK  (ROWS/RPB)       // 512

// ---------------- scratch (device globals; no allocations) ----------------
__device__ int   g_nbr[ROWS * MAXN];
__device__ int   g_cnt[ROWS];
__device__ float g_dinv[ROWS];
__device__ float g_bufA[ROWS * HID];
__device__ float g_bufB[ROWS * HID];
__device__ float g_pool[NBLK * HID];    // per-block pool partials

// ---------------------------------------------------------------------------
// K1: one warp per adjacency row. Load all 8 float4 up-front (MLP=8), then
// scan + store ELL neighbor list + dinv. 128MB read once -> HBM-bound.
// ---------------------------------------------------------------------------
__global__ void k_adj(const float4* __restrict__ adj4) {
    int gtid = blockIdx.x * blockDim.x + threadIdx.x;
    int row  = gtid >> 5;
    int lane = gtid & 31;
    if (row >= ROWS) return;

    const float4* rp = adj4 + (size_t)row * (NN / 4);
    float4 v[8];
    #pragma unroll
    for (int k = 0; k < 8; ++k) v[k] = rp[k * 32 + lane];

    int base = row * MAXN;
    int cnt = 0;
    #pragma unroll
    for (int k = 0; k < 8; ++k) {
        int col0 = (k * 32 + lane) * 4;
        int m = (v[k].x != 0.f ? 1 : 0) | (v[k].y != 0.f ? 2 : 0)
              | (v[k].z != 0.f ? 4 : 0) | (v[k].w != 0.f ? 8 : 0);
        int c = __popc(m);
        int x = c;
        #pragma unroll
        for (int d = 1; d < 32; d <<= 1) {
            int y = __shfl_up_sync(0xffffffffu, x, d);
            if (lane >= d) x += y;
        }
        int w   = cnt + x - c;
        int tot = __shfl_sync(0xffffffffu, x, 31);
        if (m & 1) { if (w < MAXN) g_nbr[base + w] = col0;     w++; }
        if (m & 2) { if (w < MAXN) g_nbr[base + w] = col0 + 1; w++; }
        if (m & 4) { if (w < MAXN) g_nbr[base + w] = col0 + 2; w++; }
        if (m & 8) { if (w < MAXN) g_nbr[base + w] = col0 + 3; w++; }
        cnt += tot;
    }
    if (lane == 0) {
        g_cnt[row]  = cnt;
        g_dinv[row] = rsqrtf((float)(cnt > 0 ? cnt : 1));
    }
}

// ---------------------------------------------------------------------------
// K2: z0[row] = dinv[row] * (x[row] @ W1).  Block = 256 thr, 4 groups of 64,
// each group does 16 rows. W1 column cached in registers (once per block).
// ---------------------------------------------------------------------------
__global__ void __launch_bounds__(256) k_lin0(const float* __restrict__ x,
                                              const float* __restrict__ W1,
                                              float* __restrict__ out) {
    int tid = threadIdx.x;
    int g   = tid >> 6;
    int t   = tid & 63;
    int R0  = blockIdx.x * RPB;

    __shared__ float sx[RPB * ND];     // 64 rows of x
    __shared__ float sdinv[RPB];

    float wreg[ND];
    #pragma unroll
    for (int c = 0; c < ND; ++c) wreg[c] = W1[c * HID + t];

    for (int i = tid; i < RPB * ND; i += 256) sx[i] = x[(size_t)R0 * ND + i];
    if (tid < RPB) sdinv[tid] = g_dinv[R0 + tid];
    __syncthreads();

    #pragma unroll 4
    for (int rr = 0; rr < 16; ++rr) {
        int r = g * 16 + rr;
        const float* xr = sx + r * ND;
        float a = 0.f;
        #pragma unroll
        for (int c = 0; c < ND; ++c) a = fmaf(xr[c], wreg[c], a);
        out[(size_t)(R0 + r) * HID + t] = a * sdinv[r];
    }
}

// ---------------------------------------------------------------------------
// K3: fused aggregation layer. Block = 256 thr, 64 rows, ELL indices staged
// in smem, next-layer weight column in registers.
//   s  = sum_{j in nbr(i)} zin[j]     (zin pre-scaled by dinv_j)
//   h  = relu(dinv_i * s + bias)
//   HAS_MV:  out[row] = dinv_i * (h @ Wnext)
//   !HAS_MV: out[blk] = per-block pool partial sum of h
// ---------------------------------------------------------------------------
template <int HAS_MV>
__global__ void __launch_bounds__(256) k_agg(const float* __restrict__ zin,
                                             const float* __restrict__ bias,
                                             const float* __restrict__ Wnext,
                                             float* __restrict__ out) {
    int tid = threadIdx.x;
    int g   = tid >> 6;
    int t   = tid & 63;
    int R0  = blockIdx.x * RPB;
    int bbase = (R0 >> 10) << 10;            // batch * N (RPB divides NN)

    __shared__ int   sidx[RPB * MAXN];       // 16 KB
    __shared__ int   scnt[RPB];
    __shared__ float sdinv[RPB];
    __shared__ float sbias[HID];
    __shared__ float sh[4][HID];
    __shared__ float part[256];

    float wreg[HID];
    if (HAS_MV) {
        #pragma unroll
        for (int c = 0; c < HID; ++c) wreg[c] = Wnext[c * HID + t];
    }

    {   // stage ELL lists (coalesced int4) + row metadata + bias
        const int4* src = (const int4*)(g_nbr + (size_t)R0 * MAXN);
        int4* dst = (int4*)sidx;
        #pragma unroll
        for (int i = 0; i < RPB * MAXN / 4 / 256; ++i)
            dst[tid + i * 256] = src[tid + i * 256];
        if (tid < RPB) {
            int c = g_cnt[R0 + tid];
            scnt[tid]  = c > MAXN ? MAXN : c;
            sdinv[tid] = g_dinv[R0 + tid];
        }
        if (tid < HID) sbias[tid] = bias[tid];
    }
    __syncthreads();

    const float* zb = zin + (size_t)bbase * HID + t;
    float pacc = 0.f;

    for (int rr = 0; rr < 16; ++rr) {
        int r = g * 16 + rr;
        int cnt = scnt[r];
        float di = sdinv[r];
        const int* idx = sidx + r * MAXN;

        float acc = 0.f;
        int k = 0;
        for (; k + 4 <= cnt; k += 4) {
            int i0 = idx[k], i1 = idx[k+1], i2 = idx[k+2], i3 = idx[k+3];
            float v0 = zb[i0 * HID];
            float v1 = zb[i1 * HID];
            float v2 = zb[i2 * HID];
            float v3 = zb[i3 * HID];
            acc += (v0 + v1) + (v2 + v3);
        }
        for (; k < cnt; ++k) acc += zb[idx[k] * HID];

        float h = fmaxf(fmaf(di, acc, sbias[t]), 0.f);

        if (HAS_MV) {
            sh[g][t] = h;
            __syncthreads();
            float a2 = 0.f;
            const float4* shv = (const float4*)sh[g];
            #pragma unroll
            for (int c4 = 0; c4 < HID / 4; ++c4) {
                float4 hv = shv[c4];
                a2 = fmaf(hv.x, wreg[4*c4+0], a2);
                a2 = fmaf(hv.y, wreg[4*c4+1], a2);
                a2 = fmaf(hv.z, wreg[4*c4+2], a2);
                a2 = fmaf(hv.w, wreg[4*c4+3], a2);
            }
            out[(size_t)(R0 + r) * HID + t] = di * a2;
            __syncthreads();
        } else {
            pacc += h;
        }
    }

    if (!HAS_MV) {
        part[tid] = pacc;
        __syncthreads();
        if (tid < HID)
            out[blockIdx.x * HID + tid] =
                part[tid] + part[tid + 64] + part[tid + 128] + part[tid + 192];
    }
}

// ---------------------------------------------------------------------------
// K4: per batch: pooled = mean over 16 block partials; relu(pooled@Wf1+bf1)
//     @ Wf2 + bf2.  One 128-thread block per batch.
// ---------------------------------------------------------------------------
__global__ void k_final(const float* __restrict__ pool,
                        const float* __restrict__ Wf1, const float* __restrict__ bf1,
                        const float* __restrict__ Wf2, const float* __restrict__ bf2,
                        float* __restrict__ out) {
    int b   = blockIdx.x;
    int tid = threadIdx.x;           // 128 threads
    __shared__ float pooled[HID];
    __shared__ float hred[HEADD];

    if (tid < HID) {
        float s = 0.f;
        #pragma unroll
        for (int i = 0; i < NN / RPB / 2; ++i)   // 16 partials per batch... NN/RPB=16
            s += pool[(b * (NN / RPB) + i) * HID + tid];
        #pragma unroll
        for (int i = NN / RPB / 2; i < NN / RPB; ++i)
            s += pool[(b * (NN / RPB) + i) * HID + tid];
        pooled[tid] = s * (1.f / NN);
    }
    __syncthreads();

    float a = bf1[tid];
    #pragma unroll
    for (int c = 0; c < HID; ++c) a = fmaf(pooled[c], Wf1[c * HEADD + tid], a);
    hred[tid] = fmaxf(a, 0.f) * Wf2[tid];
    __syncthreads();

    if (tid < 32) {
        float s = hred[tid] + hred[tid + 32] + hred[tid + 64] + hred[tid + 96];
        #pragma unroll
        for (int d = 16; d; d >>= 1) s += __shfl_down_sync(0xffffffffu, s, d);
        if (tid == 0) out[b] = s + bf2[0];
    }
}

// ---------------------------------------------------------------------------
extern "C" void kernel_launch(void* const* d_in, const int* in_sizes, int n_in,
                              void* d_out, int out_size) {
    const float* x    = (const float*)d_in[0];
    const float* adj  = (const float*)d_in[1];
    const float* W1   = (const float*)d_in[2];
    const float* b1   = (const float*)d_in[3];
    const float* W2   = (const float*)d_in[4];
    const float* b2   = (const float*)d_in[5];
    const float* W3   = (const float*)d_in[6];
    const float* b3   = (const float*)d_in[7];
    const float* Wf1  = (const float*)d_in[8];
    const float* bf1  = (const float*)d_in[9];
    const float* Wf2  = (const float*)d_in[10];
    const float* bf2  = (const float*)d_in[11];
    float* out = (float*)d_out;

    float *bufA, *bufB, *pool;
    cudaGetSymbolAddress((void**)&bufA, g_bufA);
    cudaGetSymbolAddress((void**)&bufB, g_bufB);
    cudaGetSymbolAddress((void**)&pool, g_pool);

    k_adj<<<ROWS * 32 / 256, 256>>>((const float4*)adj);       // ELL + dinv
    k_lin0<<<NBLK, 256>>>(x, W1, bufA);                        // z0
    k_agg<1><<<NBLK, 256>>>(bufA, b1, W2, bufB);               // layer1 -> z1
    k_agg<1><<<NBLK, 256>>>(bufB, b2, W3, bufA);               // layer2 -> z2
    k_agg<0><<<NBLK, 256>>>(bufA, b3, nullptr, pool);          // layer3 -> pool partials
    k_final<<<BB, HEADD>>>(pool, Wf1, bf1, Wf2, bf2, out);     // head
}

// round 3
// speedup vs baseline: 1.6319x; 1.6319x over previous
#include <cuda_runtime.h>
#include <cstdint>

#define BB    32
#define NN    1024
#define ND    14
#define HID   64
#define HEADD 128
#define MAXN  64
#define ROWS  (BB*NN)          // 32768
#define RPB   64               // rows per block in agg kernels
#define NBLK  (ROWS/RPB)       // 512
#define PAD   66               // padded h-row stride (floats), keeps float2 aligned

// ---------------- scratch (device globals; no allocations) ----------------
__device__ unsigned short g_nbr[ROWS * MAXN];   // ELL neighbor lists (cols < 1024)
__device__ int   g_cnt[ROWS];
__device__ float g_dinv[ROWS];
__device__ float g_bufA[ROWS * HID];
__device__ float g_bufB[ROWS * HID];
__device__ float g_pool[NBLK * HID];            // per-block pool partials

// ---------------------------------------------------------------------------
// K1: one warp per adjacency row. Load 8 float4 up-front (MLP=8), warp-scan,
// store uint16 ELL list + dinv. 128MB read once -> HBM-bound (~16us floor).
// ---------------------------------------------------------------------------
__global__ void k_adj(const float4* __restrict__ adj4) {
    int gtid = blockIdx.x * blockDim.x + threadIdx.x;
    int row  = gtid >> 5;
    int lane = gtid & 31;
    if (row >= ROWS) return;

    const float4* rp = adj4 + (size_t)row * (NN / 4);
    float4 v[8];
    #pragma unroll
    for (int k = 0; k < 8; ++k) v[k] = rp[k * 32 + lane];

    int base = row * MAXN;
    int cnt = 0;
    #pragma unroll
    for (int k = 0; k < 8; ++k) {
        int col0 = (k * 32 + lane) * 4;
        int m = (v[k].x != 0.f ? 1 : 0) | (v[k].y != 0.f ? 2 : 0)
              | (v[k].z != 0.f ? 4 : 0) | (v[k].w != 0.f ? 8 : 0);
        int c = __popc(m);
        int x = c;
        #pragma unroll
        for (int d = 1; d < 32; d <<= 1) {
            int y = __shfl_up_sync(0xffffffffu, x, d);
            if (lane >= d) x += y;
        }
        int w   = cnt + x - c;
        int tot = __shfl_sync(0xffffffffu, x, 31);
        if (m & 1) { if (w < MAXN) g_nbr[base + w] = (unsigned short)col0;       w++; }
        if (m & 2) { if (w < MAXN) g_nbr[base + w] = (unsigned short)(col0 + 1); w++; }
        if (m & 4) { if (w < MAXN) g_nbr[base + w] = (unsigned short)(col0 + 2); w++; }
        if (m & 8) { if (w < MAXN) g_nbr[base + w] = (unsigned short)(col0 + 3); w++; }
        cnt += tot;
    }
    if (lane == 0) {
        g_cnt[row]  = cnt;
        g_dinv[row] = rsqrtf((float)(cnt > 0 ? cnt : 1));
    }
}

// ---------------------------------------------------------------------------
// K2: z0[row] = dinv[row] * (x[row] @ W1).  64 rows / 256-thread block,
// W1 column (14 floats) in registers.
// ---------------------------------------------------------------------------
__global__ void __launch_bounds__(256) k_lin0(const float* __restrict__ x,
                                              const float* __restrict__ W1,
                                              float* __restrict__ out) {
    int tid = threadIdx.x;
    int g   = tid >> 6;
    int t   = tid & 63;
    int R0  = blockIdx.x * RPB;

    __shared__ float sx[RPB * ND];
    __shared__ float sdinv[RPB];

    float wreg[ND];
    #pragma unroll
    for (int c = 0; c < ND; ++c) wreg[c] = W1[c * HID + t];

    for (int i = tid; i < RPB * ND; i += 256) sx[i] = x[(size_t)R0 * ND + i];
    if (tid < RPB) sdinv[tid] = g_dinv[R0 + tid];
    __syncthreads();

    #pragma unroll 4
    for (int rr = 0; rr < 16; ++rr) {
        int r = g * 16 + rr;
        const float* xr = sx + r * ND;
        float a = 0.f;
        #pragma unroll
        for (int c = 0; c < ND; ++c) a = fmaf(xr[c], wreg[c], a);
        out[(size_t)(R0 + r) * HID + t] = a * sdinv[r];
    }
}

// ---------------------------------------------------------------------------
// K3: fused aggregation layer, 64 rows / 256-thread block, TWO phases:
//  Phase 1: warp w handles rows w*8..w*8+7 alone (lane = channel pair, float2
//           gather, relu) -> writes h rows to padded smem. No barriers.
//  Phase 2 (HAS_MV): block-local 64x64x64 micro-GEMM, thread = 4 rows x 4 cols
//           register tile, W from smem (LDS.128), h broadcast from smem.
//           out[row] = dinv_i * (h @ Wnext).
//  Phase 2 (!HAS_MV): per-block pool partial of h.
// ---------------------------------------------------------------------------
template <int HAS_MV>
__global__ void __launch_bounds__(256) k_agg(const float* __restrict__ zin,
                                             const float* __restrict__ bias,
                                             const float* __restrict__ Wnext,
                                             float* __restrict__ out) {
    int tid  = threadIdx.x;
    int w    = tid >> 5;
    int lane = tid & 31;
    int R0   = blockIdx.x * RPB;
    int bbase = (R0 >> 10) << 10;                 // batch * N

    __shared__ unsigned short sidx[RPB * MAXN];   // 8 KB
    __shared__ float sh[RPB * PAD];               // 16.5 KB (padded h rows)
    __shared__ float sW[HID * HID];               // 16 KB
    __shared__ float sdinv[RPB];
    __shared__ float2 spart[8][32];               // pool partials (HAS_MV=0)

    // ---- stage: ELL lists (int4), W (float4), dinv ----
    {
        const int4* src = (const int4*)(g_nbr + (size_t)R0 * MAXN);
        int4* dst = (int4*)sidx;
        #pragma unroll
        for (int i = 0; i < RPB * MAXN * 2 / 16 / 256; ++i)   // 2 iters
            dst[tid + i * 256] = src[tid + i * 256];
        if (HAS_MV) {
            const float4* ws = (const float4*)Wnext;
            float4* wd = (float4*)sW;
            #pragma unroll
            for (int i = 0; i < HID * HID / 4 / 256; ++i)     // 4 iters
                wd[tid + i * 256] = ws[tid + i * 256];
        }
        if (tid < RPB) sdinv[tid] = g_dinv[R0 + tid];
    }
    __syncthreads();

    // ---- phase 1: gather + relu, one warp per row ----
    const float2 breg = ((const float2*)bias)[lane];
    const float2* zb = (const float2*)zin + (size_t)bbase * (HID / 2) + lane;
    float2 pacc = make_float2(0.f, 0.f);

    #pragma unroll
    for (int rr = 0; rr < 8; ++rr) {
        int r    = w * 8 + rr;
        int grow = R0 + r;
        int cnt  = g_cnt[grow]; if (cnt > MAXN) cnt = MAXN;
        float di = sdinv[r];
        const unsigned short* idx = sidx + r * MAXN;

        float ax = 0.f, ay = 0.f;
        int k = 0;
        for (; k + 4 <= cnt; k += 4) {
            int i0 = idx[k], i1 = idx[k + 1], i2 = idx[k + 2], i3 = idx[k + 3];
            float2 v0 = zb[i0 * (HID / 2)];
            float2 v1 = zb[i1 * (HID / 2)];
            float2 v2 = zb[i2 * (HID / 2)];
            float2 v3 = zb[i3 * (HID / 2)];
            ax += (v0.x + v1.x) + (v2.x + v3.x);
            ay += (v0.y + v1.y) + (v2.y + v3.y);
        }
        for (; k < cnt; ++k) {
            float2 v = zb[idx[k] * (HID / 2)];
            ax += v.x; ay += v.y;
        }
        float hx = fmaxf(fmaf(di, ax, breg.x), 0.f);
        float hy = fmaxf(fmaf(di, ay, breg.y), 0.f);
        if (HAS_MV) {
            *(float2*)(sh + r * PAD + 2 * lane) = make_float2(hx, hy);
        } else {
            pacc.x += hx; pacc.y += hy;
        }
    }

    if (!HAS_MV) {
        spart[w][lane] = pacc;
        __syncthreads();
        if (tid < 32) {
            float2 s = spart[0][tid];
            #pragma unroll
            for (int i = 1; i < 8; ++i) {
                s.x += spart[i][tid].x;
                s.y += spart[i][tid].y;
            }
            *(float2*)(out + blockIdx.x * HID + 2 * tid) = s;
        }
        return;
    }

    __syncthreads();

    // ---- phase 2: 64x64x64 micro-GEMM, 4 rows x 4 cols per thread ----
    {
        int tx = tid & 15;          // col group: cols 4*tx .. 4*tx+3
        int ty = tid >> 4;          // row group: rows 4*ty .. 4*ty+3

        float acc[4][4];
        #pragma unroll
        for (int i = 0; i < 4; ++i)
            #pragma unroll
            for (int j = 0; j < 4; ++j) acc[i][j] = 0.f;

        const float* shb = sh + (4 * ty) * PAD;
        #pragma unroll 4
        for (int c = 0; c < HID; ++c) {
            float4 wv = *(const float4*)(sW + c * HID + 4 * tx);
            float a0 = shb[0 * PAD + c];
            float a1 = shb[1 * PAD + c];
            float a2 = shb[2 * PAD + c];
            float a3 = shb[3 * PAD + c];
            acc[0][0] = fmaf(a0, wv.x, acc[0][0]);
            acc[0][1] = fmaf(a0, wv.y, acc[0][1]);
            acc[0][2] = fmaf(a0, wv.z, acc[0][2]);
            acc[0][3] = fmaf(a0, wv.w, acc[0][3]);
            acc[1][0] = fmaf(a1, wv.x, acc[1][0]);
            acc[1][1] = fmaf(a1, wv.y, acc[1][1]);
            acc[1][2] = fmaf(a1, wv.z, acc[1][2]);
            acc[1][3] = fmaf(a1, wv.w, acc[1][3]);
            acc[2][0] = fmaf(a2, wv.x, acc[2][0]);
            acc[2][1] = fmaf(a2, wv.y, acc[2][1]);
            acc[2][2] = fmaf(a2, wv.z, acc[2][2]);
            acc[2][3] = fmaf(a2, wv.w, acc[2][3]);
            acc[3][0] = fmaf(a3, wv.x, acc[3][0]);
            acc[3][1] = fmaf(a3, wv.y, acc[3][1]);
            acc[3][2] = fmaf(a3, wv.z, acc[3][2]);
            acc[3][3] = fmaf(a3, wv.w, acc[3][3]);
        }

        #pragma unroll
        for (int i = 0; i < 4; ++i) {
            int r = 4 * ty + i;
            float di = sdinv[r];
            float4 o;
            o.x = di * acc[i][0];
            o.y = di * acc[i][1];
            o.z = di * acc[i][2];
            o.w = di * acc[i][3];
            *(float4*)(out + (size_t)(R0 + r) * HID + 4 * tx) = o;
        }
    }
}

// ---------------------------------------------------------------------------
// K4: per batch: pooled = mean of 16 block partials; relu(pooled@Wf1+bf1)@Wf2+bf2
// ---------------------------------------------------------------------------
__global__ void k_final(const float* __restrict__ pool,
                        const float* __restrict__ Wf1, const float* __restrict__ bf1,
                        const float* __restrict__ Wf2, const float* __restrict__ bf2,
                        float* __restrict__ out) {
    int b   = blockIdx.x;
    int tid = threadIdx.x;           // 128 threads
    __shared__ float pooled[HID];
    __shared__ float hred[HEADD];

    if (tid < HID) {
        float s = 0.f;
        #pragma unroll
        for (int i = 0; i < NN / RPB; ++i)
            s += pool[(b * (NN / RPB) + i) * HID + tid];
        pooled[tid] = s * (1.f / NN);
    }
    __syncthreads();

    float a = bf1[tid];
    #pragma unroll
    for (int c = 0; c < HID; ++c) a = fmaf(pooled[c], Wf1[c * HEADD + tid], a);
    hred[tid] = fmaxf(a, 0.f) * Wf2[tid];
    __syncthreads();

    if (tid < 32) {
        float s = hred[tid] + hred[tid + 32] + hred[tid + 64] + hred[tid + 96];
        #pragma unroll
        for (int d = 16; d; d >>= 1) s += __shfl_down_sync(0xffffffffu, s, d);
        if (tid == 0) out[b] = s + bf2[0];
    }
}

// ---------------------------------------------------------------------------
extern "C" void kernel_launch(void* const* d_in, const int* in_sizes, int n_in,
                              void* d_out, int out_size) {
    const float* x    = (const float*)d_in[0];
    const float* adj  = (const float*)d_in[1];
    const float* W1   = (const float*)d_in[2];
    const float* b1   = (const float*)d_in[3];
    const float* W2   = (const float*)d_in[4];
    const float* b2   = (const float*)d_in[5];
    const float* W3   = (const float*)d_in[6];
    const float* b3   = (const float*)d_in[7];
    const float* Wf1  = (const float*)d_in[8];
    const float* bf1  = (const float*)d_in[9];
    const float* Wf2  = (const float*)d_in[10];
    const float* bf2  = (const float*)d_in[11];
    float* out = (float*)d_out;

    float *bufA, *bufB, *pool;
    cudaGetSymbolAddress((void**)&bufA, g_bufA);
    cudaGetSymbolAddress((void**)&bufB, g_bufB);
    cudaGetSymbolAddress((void**)&pool, g_pool);

    k_adj<<<ROWS * 32 / 256, 256>>>((const float4*)adj);       // ELL + dinv
    k_lin0<<<NBLK, 256>>>(x, W1, bufA);                        // z0
    k_agg<1><<<NBLK, 256>>>(bufA, b1, W2, bufB);               // layer1 -> z1
    k_agg<1><<<NBLK, 256>>>(bufB, b2, W3, bufA);               // layer2 -> z2
    k_agg<0><<<NBLK, 256>>>(bufA, b3, nullptr, pool);          // layer3 -> pool partials
    k_final<<<BB, HEADD>>>(pool, Wf1, bf1, Wf2, bf2, out);     // head
}